// round 15
// baseline (speedup 1.0000x reference)
#include <cuda_runtime.h>

// Hopf oscillator scan — R15: R10 winner with block=128 (single variable).
// R6 regressed with (128 + loop-split); R7 proved the split alone causes the
// full regression at block=256 — so block=128 was never isolated on good
// codegen. Theory: grid 2048x128 cuts per-SM whole-block warp skew from
// 16.7% (7 vs 6 blocks of 8 warps) to 7.7% (14 vs 13 blocks of 4 warps),
// trimming the straggler-SM tail. Everything else identical to R10.

#define HOPF_DT      0.01f
#define HOPF_SCALER  20.0f

static constexpr int BS  = 8;
static constexpr int T   = 64;
static constexpr int CPB = 32 * 32 * 32;   // channels per batch = 32768
static constexpr int PF  = 4;              // prefetch ring depth (power of 2)

__global__ __launch_bounds__(128, 14)
void hopf_scan_kernel(const float* __restrict__ Xr,
                      const float* __restrict__ Xi,
                      const float* __restrict__ Om,
                      float* __restrict__ OutR,
                      float* __restrict__ OutI)
{
    const int u = blockIdx.x * blockDim.x + threadIdx.x;  // 0..262143
    const int b = u >> 15;            // / CPB
    const int c = u & (CPB - 1);      // % CPB

    const float om = Om[c];

    float r = 1.0f, phi = 0.0f, cs = 1.0f, sn = 0.0f;

    const int base = (b * T) * CPB + c;

    // Preload stages t = 0..PF-2 (streaming reads: no L2 pollution, which
    // preserves L2 capacity for buffering the write stream)
    float xrb[PF], xib[PF];
#pragma unroll
    for (int p = 0; p < PF - 1; ++p) {
        xrb[p] = __ldcs(Xr + base + p * CPB);
        xib[p] = __ldcs(Xi + base + p * CPB);
    }

    // Fully unrolled: t is a compile-time constant per iteration — the tail
    // predicate folds away, ring slots become registers, offsets become
    // immediates, and ptxas batches loads ahead of the compute chain.
#pragma unroll
    for (int t = 0; t < T; ++t) {
        if (t + PF - 1 < T) {   // compile-time predicate
            const int tp = t + PF - 1;
            xrb[tp & (PF - 1)] = __ldcs(Xr + base + tp * CPB);
            xib[tp & (PF - 1)] = __ldcs(Xi + base + tp * CPB);
        }

        const float xr = xrb[t & (PF - 1)];
        const float xi = xib[t & (PF - 1)];

        const float input_r   = HOPF_SCALER * xr * cs;
        const float input_phi = HOPF_SCALER * xi * sn;
        r   = r + ((1.0f - r * r) * r + input_r) * HOPF_DT;
        phi = phi + (om - input_phi) * HOPF_DT;
        __sincosf(phi, &sn, &cs);

        const int off = base + t * CPB;
        OutR[off] = r * cs;   // default policy: L2 buffers the write stream
        OutI[off] = r * sn;
    }
}

extern "C" void kernel_launch(void* const* d_in, const int* in_sizes, int n_in,
                              void* d_out, int out_size)
{
    const float* Xr = (const float*)d_in[0];
    const float* Xi = (const float*)d_in[1];
    const float* Om = (const float*)d_in[2];

    float* out  = (float*)d_out;
    const int n_elem = BS * T * CPB;            // 16,777,216 per output tensor
    float* OutR = out;
    float* OutI = out + n_elem;

    const int n_threads = BS * CPB;             // 262144
    hopf_scan_kernel<<<n_threads / 128, 128>>>(Xr, Xi, Om, OutR, OutI);
}

// round 16
// speedup vs baseline: 1.0343x; 1.0343x over previous
#include <cuda_runtime.h>

// Hopf oscillator scan — FINAL (R10). All variables experimentally closed:
//   vector width (float4/float2/scalar -> scalar, R1/R3/R4)
//   prefetch depth (1/4/8 -> 4, R1/R2/R5)
//   loop structure (clamped/split/full-unroll -> full unroll, R4/R6-R8)
//   ld/st codegen (asm vs intrinsics -> neutral, R9)
//   store policy (.cs vs default -> default, R10)
//   block size (256 vs 128 -> 256, R15)
//   noise floor (replays R11-R14: dur 47.6-49.2, kernel 38.7-39.9 w/ DVFS)
//
// Result: 256MB compulsory traffic at 6.6 TB/s (~83% of 8TB/s HBM3e spec),
// at the B300 path-independent LTS/DRAM ceiling minus R/W turnaround.
// Occupancy grid-limited (79%, single wave), all compute pipes <=12%,
// traffic irreducible (nonlinear scan: r^3 + sin(phi) feedback).

#define HOPF_DT      0.01f
#define HOPF_SCALER  20.0f

static constexpr int BS  = 8;
static constexpr int T   = 64;
static constexpr int CPB = 32 * 32 * 32;   // channels per batch = 32768
static constexpr int PF  = 4;              // prefetch ring depth (power of 2)

__global__ __launch_bounds__(256, 7)
void hopf_scan_kernel(const float* __restrict__ Xr,
                      const float* __restrict__ Xi,
                      const float* __restrict__ Om,
                      float* __restrict__ OutR,
                      float* __restrict__ OutI)
{
    const int u = blockIdx.x * blockDim.x + threadIdx.x;  // 0..262143
    const int b = u >> 15;            // / CPB
    const int c = u & (CPB - 1);      // % CPB

    const float om = Om[c];

    float r = 1.0f, phi = 0.0f, cs = 1.0f, sn = 0.0f;

    const int base = (b * T) * CPB + c;

    // Preload stages t = 0..PF-2 (streaming reads: no L2 pollution, which
    // preserves L2 capacity for buffering the write stream)
    float xrb[PF], xib[PF];
#pragma unroll
    for (int p = 0; p < PF - 1; ++p) {
        xrb[p] = __ldcs(Xr + base + p * CPB);
        xib[p] = __ldcs(Xi + base + p * CPB);
    }

    // Fully unrolled: t is a compile-time constant per iteration — the tail
    // predicate folds away, ring slots become registers, offsets become
    // immediates, and ptxas batches loads ahead of the compute chain.
#pragma unroll
    for (int t = 0; t < T; ++t) {
        if (t + PF - 1 < T) {   // compile-time predicate
            const int tp = t + PF - 1;
            xrb[tp & (PF - 1)] = __ldcs(Xr + base + tp * CPB);
            xib[tp & (PF - 1)] = __ldcs(Xi + base + tp * CPB);
        }

        const float xr = xrb[t & (PF - 1)];
        const float xi = xib[t & (PF - 1)];

        const float input_r   = HOPF_SCALER * xr * cs;
        const float input_phi = HOPF_SCALER * xi * sn;
        r   = r + ((1.0f - r * r) * r + input_r) * HOPF_DT;
        phi = phi + (om - input_phi) * HOPF_DT;
        __sincosf(phi, &sn, &cs);

        const int off = base + t * CPB;
        OutR[off] = r * cs;   // default policy: L2 buffers the write stream
        OutI[off] = r * sn;
    }
}

extern "C" void kernel_launch(void* const* d_in, const int* in_sizes, int n_in,
                              void* d_out, int out_size)
{
    const float* Xr = (const float*)d_in[0];
    const float* Xi = (const float*)d_in[1];
    const float* Om = (const float*)d_in[2];

    float* out  = (float*)d_out;
    const int n_elem = BS * T * CPB;            // 16,777,216 per output tensor
    float* OutR = out;
    float* OutI = out + n_elem;

    const int n_threads = BS * CPB;             // 262144
    hopf_scan_kernel<<<n_threads / 256, 256>>>(Xr, Xi, Om, OutR, OutI);
}